// round 15
// baseline (speedup 1.0000x reference)
#include <cuda_runtime.h>
#include <cuda_bf16.h>
#include <cuda_fp16.h>
#include <cstdint>

// ---------------------------------------------------------------------------
// GCN encoder: N=50000, E=500000, 128 -> 256 -> 512 -> 128
// R7 proven core (CSR gather + fp16 mma.sync 128x128 GEMMs, 2-stage pipe)
// + BN-prep inlined into consumers (11 launches)
// ---------------------------------------------------------------------------

#define MAXN 50048
#define MAXE 524288
#define EPS 1e-5f
#define SCAN_BLK 1024

__device__ float  g_dinv[MAXN];
__device__ int    g_cnt[MAXN];
__device__ int    g_rowptr[MAXN + 1];
__device__ int    g_cursor[MAXN];
__device__ int    g_bsum[64];
__device__ int2   g_adj[MAXE];                 // (src, bits(w))
__device__ __half g_agg1h[(size_t)MAXN * 128];
__device__ __half g_agg2h[(size_t)MAXN * 256];
__device__ __half g_h1[(size_t)MAXN * 256];    // fp16 raw (pre-BN)
__device__ __half g_h2[(size_t)MAXN * 512];
__device__ __half g_w1t[256 * 128];            // fp16 W1^T [N][K]
__device__ __half g_w2t[512 * 256];
__device__ __half g_wlt[128 * 512];
__device__ float2 g_stats1[256];
__device__ float2 g_stats2[512];
__device__ int    g_flag32;

// ---------------------------------------------------------------------------

__device__ __forceinline__ void red_add_v2(float2* addr, float a, float b) {
    asm volatile("red.global.add.v2.f32 [%0], {%1,%2};"
                 :: "l"(addr), "f"(a), "f"(b) : "memory");
}

__device__ __forceinline__ int load_idx(const void* ei, long long pos, int is32) {
    if (is32) return ((const int*)ei)[pos];
    return (int)(((const long long*)ei)[pos]);
}

__device__ __forceinline__ uint32_t pack_h2(float lo, float hi) {
    uint32_t u;
    asm("cvt.rn.f16x2.f32 %0, %1, %2;" : "=r"(u) : "f"(hi), "f"(lo));
    return u;
}

__device__ __forceinline__ float2 unpack_h2(uint32_t u) {
    __half2 h = *(__half2*)&u;
    return __half22float2(h);
}

__device__ __forceinline__ void cp_async16(void* sptr, const void* gptr, int src_bytes) {
    uint32_t sa = (uint32_t)__cvta_generic_to_shared(sptr);
    asm volatile("cp.async.cg.shared.global [%0], [%1], 16, %2;"
                 :: "r"(sa), "l"(gptr), "r"(src_bytes));
}

// BN (scale, shift) from raw stats — identical fp32 ops as the old k_bnprep
__device__ __forceinline__ float2 bn_ss(float2 st, float gamma, float beta, float invM) {
    float mu = st.x * invM;
    float var = st.y * invM - mu * mu;
    float sc = gamma * rsqrtf(var + EPS);
    return make_float2(sc, beta - mu * sc);
}

// --- prep0 (+fused dtype detect on block 0): zero cnt + stats ----------------
__global__ void k_prep0(const int* __restrict__ ei32, long long E,
                        int* cnt, int n, float2* st1, float2* st2,
                        int d1, int d2, int* flag) {
    int i = blockIdx.x * blockDim.x + threadIdx.x;
    if (blockIdx.x == 0) {
        long long lim = E < 8192 ? E : 8192;
        int any = 0;
        for (long long j = threadIdx.x; j < lim; j += blockDim.x)
            if (ei32[2 * j + 1] != 0) any = 1;
        if (any) atomicOr(flag, 1);
    }
    if (i < n) cnt[i] = 0;
    if (i < d1) st1[i] = make_float2(0.f, 0.f);
    if (i < d2) st2[i] = make_float2(0.f, 0.f);
}

// --- in-degree counts ---------------------------------------------------------
__global__ void k_count(const void* ei, long long E, const int* flag, int* cnt) {
    long long i = blockIdx.x * (long long)blockDim.x + threadIdx.x;
    long long stride = (long long)gridDim.x * blockDim.x;
    int is32 = *flag;
    for (; i < E; i += stride) {
        int d = load_idx(ei, E + i, is32);
        atomicAdd(&cnt[d], 1);
    }
}

// --- scan pass 1 ---------------------------------------------------------------
__global__ __launch_bounds__(SCAN_BLK) void k_scan_red(const int* __restrict__ cnt,
                                                       int* __restrict__ bsum, int n) {
    int i = blockIdx.x * SCAN_BLK + threadIdx.x;
    int v = (i < n) ? cnt[i] : 0;
    int lane = threadIdx.x & 31, wid = threadIdx.x >> 5;
#pragma unroll
    for (int off = 16; off; off >>= 1) v += __shfl_xor_sync(0xffffffffu, v, off);
    __shared__ int ws[32];
    if (lane == 0) ws[wid] = v;
    __syncthreads();
    if (wid == 0) {
        v = ws[lane];
#pragma unroll
        for (int off = 16; off; off >>= 1) v += __shfl_xor_sync(0xffffffffu, v, off);
        if (lane == 0) bsum[blockIdx.x] = v;
    }
}

// --- scan pass 2 ---------------------------------------------------------------
__global__ __launch_bounds__(SCAN_BLK) void k_scan_apply(const int* __restrict__ cnt,
                                                         const int* __restrict__ bsum, int nb,
                                                         int* __restrict__ rowptr,
                                                         int* __restrict__ cursor,
                                                         float* __restrict__ dinv, int n) {
    int tid = threadIdx.x;
    int lane = tid & 31, wid = tid >> 5;
    __shared__ int ws[32];
    __shared__ int s_off;

    int b = (tid < nb && tid < blockIdx.x) ? bsum[tid] : 0;
#pragma unroll
    for (int off = 16; off; off >>= 1) b += __shfl_xor_sync(0xffffffffu, b, off);
    if (lane == 0) ws[wid] = b;
    __syncthreads();
    if (wid == 0) {
        int w = ws[lane];
#pragma unroll
        for (int off = 16; off; off >>= 1) w += __shfl_xor_sync(0xffffffffu, w, off);
        if (lane == 0) s_off = w;
    }
    __syncthreads();
    int offset = s_off;
    __syncthreads();

    int i = blockIdx.x * SCAN_BLK + tid;
    int v = (i < n) ? cnt[i] : 0;
    int x = v;
#pragma unroll
    for (int off = 1; off < 32; off <<= 1) {
        int y = __shfl_up_sync(0xffffffffu, x, off);
        if (lane >= off) x += y;
    }
    if (lane == 31) ws[wid] = x;
    __syncthreads();
    if (wid == 0) {
        int w = ws[lane];
#pragma unroll
        for (int off = 1; off < 32; off <<= 1) {
            int y = __shfl_up_sync(0xffffffffu, w, off);
            if (lane >= off) w += y;
        }
        ws[lane] = w;
    }
    __syncthreads();
    int incl = x + (wid > 0 ? ws[wid - 1] : 0);
    int excl = incl - v + offset;
    if (i < n) {
        rowptr[i] = excl;
        cursor[i] = excl;
        dinv[i] = rsqrtf((float)v + 1.0f);
        if (i == n - 1) rowptr[n] = excl + v;
    }
}

// --- bucket-fill adjacency -------------------------------------------------------
__global__ void k_fill(const void* __restrict__ ei, long long E, const int* flag,
                       const float* __restrict__ dinv, int* __restrict__ cursor,
                       int2* __restrict__ adj) {
    long long i = blockIdx.x * (long long)blockDim.x + threadIdx.x;
    long long stride = (long long)gridDim.x * blockDim.x;
    int is32 = *flag;
    for (; i < E; i += stride) {
        int s = load_idx(ei, i, is32);
        int d = load_idx(ei, E + i, is32);
        float w = dinv[s] * dinv[d];
        int pos = atomicAdd(&cursor[d], 1);
        adj[pos] = make_int2(s, __float_as_int(w));
    }
}

// --- weight convert: all three -> fp16 transposed [N][K] --------------------------
__global__ void k_cvtw(const float* __restrict__ W1, const float* __restrict__ W2,
                       const float* __restrict__ W3,
                       __half* __restrict__ t1, __half* __restrict__ t2,
                       __half* __restrict__ t3,
                       int K1, int N1, int K2, int N2, int K3, int N3) {
    int i = blockIdx.x * blockDim.x + threadIdx.x;
    if (i < K1 * N1) {
        int k = i / N1, n = i % N1;
        t1[n * K1 + k] = __float2half_rn(W1[i]);
    }
    if (i < K2 * N2) {
        int k = i / N2, n = i % N2;
        t2[n * K2 + k] = __float2half_rn(W2[i]);
    }
    if (i < K3 * N3) {
        int k = i / N3, n = i % N3;
        t3[n * K3 + k] = __float2half_rn(W3[i]);
    }
}

// --- agg layer 1: fp32 x in, fp16 out (R7) ----------------------------------------
__global__ __launch_bounds__(256) void k_agg1(const int2* __restrict__ adj,
                                              const int* __restrict__ rowptr,
                                              const float* __restrict__ dinv,
                                              const float* __restrict__ X,
                                              __half* __restrict__ out, int N) {
    int node = (blockIdx.x * blockDim.x + threadIdx.x) >> 5;
    int lane = threadIdx.x & 31;
    if (node >= N) return;
    float w0 = dinv[node]; w0 *= w0;
    float4 a = ((const float4*)(X + (size_t)node * 128))[lane];
    float4 acc = make_float4(a.x * w0, a.y * w0, a.z * w0, a.w * w0);
    int j = rowptr[node], end = rowptr[node + 1];
    int2 e = (j < end) ? adj[j] : make_int2(0, 0);
    for (; j < end; j++) {
        int2 cur = e;
        if (j + 1 < end) e = adj[j + 1];
        float w = __int_as_float(cur.y);
        float4 s = ((const float4*)(X + (size_t)cur.x * 128))[lane];
        acc.x += w * s.x; acc.y += w * s.y;
        acc.z += w * s.z; acc.w += w * s.w;
    }
    ((uint2*)(out + (size_t)node * 128))[lane] =
        make_uint2(pack_h2(acc.x, acc.y), pack_h2(acc.z, acc.w));
}

// --- agg layer 2: fp16 h1 in, BN1 inline from raw stats, fp16 out (R7 loop) -------
__global__ __launch_bounds__(256) void k_agg2(const int2* __restrict__ adj,
                                              const int* __restrict__ rowptr,
                                              const float* __restrict__ dinv,
                                              const __half* __restrict__ X,
                                              __half* __restrict__ out, int N,
                                              const float2* __restrict__ stats,
                                              const float* __restrict__ gamma,
                                              const float* __restrict__ beta,
                                              float invM) {
    int node = (blockIdx.x * blockDim.x + threadIdx.x) >> 5;
    int lane = threadIdx.x & 31;
    if (node >= N) return;
    float2 sr[8];
#pragma unroll
    for (int j = 0; j < 8; j++) {
        int c = lane * 8 + j;
        sr[j] = bn_ss(stats[c], gamma[c], beta[c], invM);
    }

    float acc[8];
    float w0 = dinv[node]; w0 *= w0;
    {
        uint4 u = ((const uint4*)(X + (size_t)node * 256))[lane];
        float2 f0 = unpack_h2(u.x), f1 = unpack_h2(u.y);
        float2 f2 = unpack_h2(u.z), f3 = unpack_h2(u.w);
        float f[8] = {f0.x, f0.y, f1.x, f1.y, f2.x, f2.y, f3.x, f3.y};
#pragma unroll
        for (int j = 0; j < 8; j++)
            acc[j] = w0 * fmaxf(fmaf(f[j], sr[j].x, sr[j].y), 0.f);
    }
    int j = rowptr[node], end = rowptr[node + 1];
    int2 e = (j < end) ? adj[j] : make_int2(0, 0);
    for (; j < end; j++) {
        int2 cur = e;
        if (j + 1 < end) e = adj[j + 1];
        float w = __int_as_float(cur.y);
        uint4 u = ((const uint4*)(X + (size_t)cur.x * 256))[lane];
        float2 f0 = unpack_h2(u.x), f1 = unpack_h2(u.y);
        float2 f2 = unpack_h2(u.z), f3 = unpack_h2(u.w);
        float f[8] = {f0.x, f0.y, f1.x, f1.y, f2.x, f2.y, f3.x, f3.y};
#pragma unroll
        for (int jj = 0; jj < 8; jj++)
            acc[jj] += w * fmaxf(fmaf(f[jj], sr[jj].x, sr[jj].y), 0.f);
    }
    uint4 o;
    o.x = pack_h2(acc[0], acc[1]);
    o.y = pack_h2(acc[2], acc[3]);
    o.z = pack_h2(acc[4], acc[5]);
    o.w = pack_h2(acc[6], acc[7]);
    ((uint4*)(out + (size_t)node * 256))[lane] = o;
}

// ---------------------------------------------------------------------------
// fp16 mma.sync pipelined GEMM (R7 core): 128x128 tile, 8 warps (32x64),
// BK=32, cp.async 2-stage. Fused bias + fp32 BN stats, fp16 C.
// ---------------------------------------------------------------------------
#define GBM 128
#define GBN 128
#define HASTR 40
#define HTSZ (128 * HASTR)
#define SMEM_H ((4 * HTSZ) * 2)
#define SMEM_FINH (SMEM_H + 512 * 8)

__global__ __launch_bounds__(256) void k_gemm_h(const __half* __restrict__ A,
                                                const __half* __restrict__ Bt,
                                                const float* __restrict__ bias,
                                                __half* __restrict__ C,
                                                float2* __restrict__ stats,
                                                int M, int N, int K) {
    extern __shared__ __half smh[];
    __half* As = smh;
    __half* Bs = smh + 2 * HTSZ;

    const int tid  = threadIdx.x;
    const int lane = tid & 31;
    const int warpId = tid >> 5;
    const int warpM = warpId & 3;
    const int warpN = warpId >> 2;
    const int g = lane >> 2;
    const int t = lane & 3;
    const int bm = blockIdx.y * GBM;
    const int bn = blockIdx.x * GBN;

    const int l_row = tid >> 2;
    const int l_chk = (tid & 3) * 8;

    float4 acc[2][8];
#pragma unroll
    for (int i = 0; i < 2; i++)
#pragma unroll
        for (int j = 0; j < 8; j++)
            acc[i][j] = make_float4(0.f, 0.f, 0.f, 0.f);

    auto load_stage = [&](int stg, int k0) {
        __half* pa = As + stg * HTSZ;
        __half* pb = Bs + stg * HTSZ;
#pragma unroll
        for (int i = 0; i < 2; i++) {
            int row = i * 64 + l_row;
            int gm = bm + row;
            int ok = (gm < M) ? 16 : 0;
            int gmc = min(gm, M - 1);
            cp_async16(pa + row * HASTR + l_chk, A + (size_t)gmc * K + k0 + l_chk, ok);
        }
#pragma unroll
        for (int i = 0; i < 2; i++) {
            int row = i * 64 + l_row;
            cp_async16(pb + row * HASTR + l_chk, Bt + (size_t)(bn + row) * K + k0 + l_chk, 16);
        }
    };

    const int nk = K / 32;
    load_stage(0, 0);
    asm volatile("cp.async.commit_group;");

    for (int tk = 0; tk < nk; tk++) {
        if (tk + 1 < nk) {
            load_stage((tk + 1) & 1, (tk + 1) * 32);
            asm volatile("cp.async.commit_group;");
            asm volatile("cp.async.wait_group 1;");
        } else {
            asm volatile("cp.async.wait_group 0;");
        }
        __syncthreads();

        const __half* pa = As + (tk & 1) * HTSZ;
        const __half* pb = Bs + (tk & 1) * HTSZ;
#pragma unroll
        for (int kk = 0; kk < 32; kk += 16) {
            uint32_t afrag[2][4];
            uint32_t bfrag[8][2];
#pragma unroll
            for (int im = 0; im < 2; im++) {
                const __half* base = pa + (warpM * 32 + im * 16 + g) * HASTR + kk + 2 * t;
                afrag[im][0] = *(const uint32_t*)(base);
                afrag[im][1] = *(const uint32_t*)(base + 8 * HASTR);
                afrag[im][2] = *(const uint32_t*)(base + 8);
                afrag[im][3] = *(const uint32_t*)(base + 8 * HASTR + 8);
            }
#pragma unroll
            for (int jn = 0; jn < 8; jn++) {
                const __half* base = pb + (warpN * 64 + jn * 8 + g) * HASTR + kk + 2 * t;
                bfrag[jn][0] = *(const uint32_t*)(base);
                bfrag[jn][1] = *(const uint32_t*)(base + 8);
            }
#pragma unroll
            for (int im = 0; im < 2; im++)
#pragma unroll
                for (int jn = 0; jn < 8; jn++) {
                    float4& c = acc[im][jn];
                    asm volatile(
                        "mma.sync.aligned.m16n8k16.row.col.f32.f16.f16.f32 "
                        "{%0,%1,%2,%3}, {%4,%5,%6,%7}, {%8,%9}, {%0,%1,%2,%3};"
                        : "+f"(c.x), "+f"(c.y), "+f"(c.z), "+f"(c.w)
                        : "r"(afrag[im][0]), "r"(afrag[im][1]),
                          "r"(afrag[im][2]), "r"(afrag[im][3]),
                          "r"(bfrag[jn][0]), "r"(bfrag[jn][1]));
                }
        }
        __syncthreads();
    }

#pragma unroll
    for (int jn = 0; jn < 8; jn++) {
        int col = bn + warpN * 64 + jn * 8 + 2 * t;
        float bx = bias[col], by = bias[col + 1];
        float s0 = 0.f, q0 = 0.f, s1 = 0.f, q1 = 0.f;
#pragma unroll
        for (int im = 0; im < 2; im++) {
            int row0 = bm + warpM * 32 + im * 16 + g;
            float4 c = acc[im][jn];
            if (row0 < M) {
                float ox = c.x + bx, oy = c.y + by;
                *(uint32_t*)(C + (size_t)row0 * N + col) = pack_h2(ox, oy);
                s0 += ox; q0 += ox * ox; s1 += oy; q1 += oy * oy;
            }
            if (row0 + 8 < M) {
                float oz = c.z + bx, ow = c.w + by;
                *(uint32_t*)(C + (size_t)(row0 + 8) * N + col) = pack_h2(oz, ow);
                s0 += oz; q0 += oz * oz; s1 += ow; q1 += ow * ow;
            }
        }
#pragma unroll
        for (int m = 4; m < 32; m <<= 1) {
            s0 += __shfl_xor_sync(0xffffffffu, s0, m);
            q0 += __shfl_xor_sync(0xffffffffu, q0, m);
            s1 += __shfl_xor_sync(0xffffffffu, s1, m);
            q1 += __shfl_xor_sync(0xffffffffu, q1, m);
        }
        if (g == 0) {
            red_add_v2(&stats[col], s0, q0);
            red_add_v2(&stats[col + 1], s1, q1);
        }
    }
}

// ---------------------------------------------------------------------------
// Final fp16 GEMM (R7 core): BN2 inline from raw stats during smem staging,
// BN2+ReLU applied to A frags at build. fp32 out.
// ---------------------------------------------------------------------------
__global__ __launch_bounds__(256) void k_gemm_finh(const __half* __restrict__ A,
                                                   const __half* __restrict__ Bt,
                                                   const float* __restrict__ bias,
                                                   float* __restrict__ C,
                                                   const float2* __restrict__ stats,
                                                   const float* __restrict__ gamma,
                                                   const float* __restrict__ beta,
                                                   float invM,
                                                   int M, int N, int K) {
    extern __shared__ __half smh[];
    __half* As = smh;
    __half* Bs = smh + 2 * HTSZ;
    float2* ssm = (float2*)(smh + 4 * HTSZ);

    const int tid  = threadIdx.x;
    const int lane = tid & 31;
    const int warpId = tid >> 5;
    const int warpM = warpId & 3;
    const int warpN = warpId >> 2;
    const int g = lane >> 2;
    const int t = lane & 3;
    const int bm = blockIdx.y * GBM;
    const int bn = blockIdx.x * GBN;

    for (int c = tid; c < K; c += 256)
        ssm[c] = bn_ss(stats[c], gamma[c], beta[c], invM);

    const int l_row = tid >> 2;
    const int l_chk = (tid & 3) * 8;

    float4 acc[2][8];
#pragma unroll
    for (int i = 0; i < 2; i++)
#pragma unroll
        for (int j = 0; j < 8; j++)
            acc[i][j] = make_float4(0.f, 0.f, 0.f, 0.f);

    auto load_stage = [&](int stg, int k0) {
        __half* pa = As + stg * HTSZ;
        __half* pb = Bs + stg * HTSZ;
#pragma unroll
        for (int i = 0; i < 2; i++) {
            int row = i * 64 + l_row;
            int gm = bm + row;
            int ok = (gm < M) ? 16 : 0;
            int gmc = min(gm, M - 1);
            cp_async16(pa + row * HASTR + l_chk, A + (size_t)gmc * K + k0 + l_chk, ok);
        }
#pragma unroll
        for (int i = 0; i < 2; i++) {
            int row = i * 64 + l_row;
            cp_async16(pb + row * HASTR + l_chk, Bt + (size_t)(bn + row) * K + k0 + l_chk, 16);
        }
    };

    const int nk = K / 32;
    load_stage(0, 0);
    asm volatile("cp.async.commit_group;");

    for (int tk = 0; tk < nk; tk++) {
        if (tk + 1 < nk) {
            load_stage((tk + 1) & 1, (tk + 1) * 32);
            asm volatile("cp.async.commit_group;");
            asm volatile("cp.async.wait_group 1;");
        } else {
            asm volatile("cp.async.wait_group 0;");
        }
        __syncthreads();

        const __half* pa = As + (tk & 1) * HTSZ;
        const __half* pb = Bs + (tk & 1) * HTSZ;
        const int kbase = tk * 32;
#pragma unroll
        for (int kk = 0; kk < 32; kk += 16) {
            int kc = kbase + kk + 2 * t;
            float2 s0 = ssm[kc],     s1 = ssm[kc + 1];
            float2 s2 = ssm[kc + 8], s3 = ssm[kc + 9];
            uint32_t afrag[2][4];
            uint32_t bfrag[8][2];
#pragma unroll
            for (int im = 0; im < 2; im++) {
                const __half* base = pa + (warpM * 32 + im * 16 + g) * HASTR + kk + 2 * t;
                float2 f0 = unpack_h2(*(const uint32_t*)(base));
                float2 f1 = unpack_h2(*(const uint32_t*)(base + 8 * HASTR));
                float2 f2 = unpack_h2(*(const uint32_t*)(base + 8));
                float2 f3 = unpack_h2(*(const uint32_t*)(base + 8 * HASTR + 8));
                afrag[im][0] = pack_h2(fmaxf(fmaf(f0.x, s0.x, s0.y), 0.f),
                                       fmaxf(fmaf(f0.y, s1.x, s1.y), 0.f));
                afrag[im][1] = pack_h2(fmaxf(fmaf(f1.x, s0.x, s0.y), 0.f),
                                       fmaxf(fmaf(f1.y, s1.x, s1.y), 0.f));
                afrag[im][2] = pack_h2(fmaxf(fmaf(f2.x, s2.x, s2.y), 0.f),
                                       fmaxf(fmaf(f2.y, s3.x, s3.y), 0.f));
                afrag[im][3] = pack_h2(fmaxf(fmaf(f3.x, s2.x, s2.y), 0.f),
                                       fmaxf(fmaf(f3.y, s3.x, s3.y), 0.f));
            }
#pragma unroll
            for (int jn = 0; jn < 8; jn++) {
                const __half* base = pb + (warpN * 64 + jn * 8 + g) * HASTR + kk + 2 * t;
                bfrag[jn][0] = *(const uint32_t*)(base);
                bfrag[jn][1] = *(const uint32_t*)(base + 8);
            }
#pragma unroll
            for (int im = 0; im < 2; im++)
#pragma unroll
                for (int jn = 0; jn < 8; jn++) {
                    float4& c = acc[im][jn];
                    asm volatile(
                        "mma.sync.aligned.m16n8k16.row.col.f32.f16.f16.f32 "
                        "{%0,%1,%2,%3}, {%4,%5,%6,%7}, {%8,%9}, {%0,%1,%2,%3};"
                        : "+f"(c.x), "+f"(c.y), "+f"(c.z), "+f"(c.w)
                        : "r"(afrag[im][0]), "r"(afrag[im][1]),
                          "r"(afrag[im][2]), "r"(afrag[im][3]),
                          "r"(bfrag[jn][0]), "r"(bfrag[jn][1]));
                }
        }
        __syncthreads();
    }

#pragma unroll
    for (int jn = 0; jn < 8; jn++) {
        int col = bn + warpN * 64 + jn * 8 + 2 * t;
        float bx = bias[col], by = bias[col + 1];
#pragma unroll
        for (int im = 0; im < 2; im++) {
            int row0 = bm + warpM * 32 + im * 16 + g;
            float4 c = acc[im][jn];
            if (row0 < M)
                *(float2*)(C + (size_t)row0 * N + col) = make_float2(c.x + bx, c.y + by);
            if (row0 + 8 < M)
                *(float2*)(C + (size_t)(row0 + 8) * N + col) = make_float2(c.z + bx, c.w + by);
        }
    }
}

// ---------------------------------------------------------------------------

extern "C" void kernel_launch(void* const* d_in, const int* in_sizes, int n_in,
                              void* d_out, int out_size) {
    const float* x      = (const float*)d_in[0];
    const void*  ei     = d_in[1];
    const float* W1     = (const float*)d_in[2];
    const float* b1     = (const float*)d_in[3];
    const float* gamma1 = (const float*)d_in[4];
    const float* beta1  = (const float*)d_in[5];
    const float* W2     = (const float*)d_in[6];
    const float* b2     = (const float*)d_in[7];
    const float* gamma2 = (const float*)d_in[8];
    const float* beta2  = (const float*)d_in[9];
    const float* Wl     = (const float*)d_in[10];
    const float* bl     = (const float*)d_in[11];

    const int H1   = in_sizes[3];
    const int H2   = in_sizes[7];
    const int DOUT = in_sizes[11];
    const int DIN  = in_sizes[2] / H1;
    const int N    = in_sizes[0] / DIN;
    const long long E = in_sizes[1] / 2;
    const float invM = 1.0f / (float)N;

    float *dinv;
    __half *agg1h, *agg2h, *h1, *h2, *w1t, *w2t, *wlt;
    float2 *stats1, *stats2;
    int *cnt, *rowptr, *cursor, *flag, *bsum;
    int2* adj;
    cudaGetSymbolAddress((void**)&dinv,   g_dinv);
    cudaGetSymbolAddress((void**)&cnt,    g_cnt);
    cudaGetSymbolAddress((void**)&rowptr, g_rowptr);
    cudaGetSymbolAddress((void**)&cursor, g_cursor);
    cudaGetSymbolAddress((void**)&bsum,   g_bsum);
    cudaGetSymbolAddress((void**)&adj,    g_adj);
    cudaGetSymbolAddress((void**)&agg1h,  g_agg1h);
    cudaGetSymbolAddress((void**)&agg2h,  g_agg2h);
    cudaGetSymbolAddress((void**)&h1,     g_h1);
    cudaGetSymbolAddress((void**)&h2,     g_h2);
    cudaGetSymbolAddress((void**)&w1t,    g_w1t);
    cudaGetSymbolAddress((void**)&w2t,    g_w2t);
    cudaGetSymbolAddress((void**)&wlt,    g_wlt);
    cudaGetSymbolAddress((void**)&stats1, g_stats1);
    cudaGetSymbolAddress((void**)&stats2, g_stats2);
    cudaGetSymbolAddress((void**)&flag,   g_flag32);

    float* out = (float*)d_out;

    cudaFuncSetAttribute(k_gemm_h,    cudaFuncAttributeMaxDynamicSharedMemorySize, SMEM_H);
    cudaFuncSetAttribute(k_gemm_finh, cudaFuncAttributeMaxDynamicSharedMemorySize, SMEM_FINH);

    const int scanBlocks = (N + SCAN_BLK - 1) / SCAN_BLK;
    const int aggBlocks = (int)(((long long)N * 32 + 255) / 256);

    // 11 launches total
    k_prep0<<<(N + 255) / 256, 256>>>((const int*)ei, E, cnt, N, stats1, stats2, H1, H2, flag);
    k_count<<<1024, 256>>>(ei, E, flag, cnt);
    k_scan_red<<<scanBlocks, SCAN_BLK>>>(cnt, bsum, N);
    k_scan_apply<<<scanBlocks, SCAN_BLK>>>(cnt, bsum, scanBlocks, rowptr, cursor, dinv, N);
    k_fill<<<1024, 256>>>(ei, E, flag, dinv, cursor, adj);

    k_agg1<<<aggBlocks, 256>>>(adj, rowptr, dinv, x, agg1h, N);

    k_cvtw<<<(H1 * H2 + 255) / 256, 256>>>(W1, W2, Wl, w1t, w2t, wlt,
                                           DIN, H1, H1, H2, H2, DOUT);

    {
        dim3 grid(H1 / GBN, (N + GBM - 1) / GBM);
        k_gemm_h<<<grid, 256, SMEM_H>>>(agg1h, w1t, b1, h1, stats1, N, H1, DIN);
    }

    k_agg2<<<aggBlocks, 256>>>(adj, rowptr, dinv, h1, agg2h, N,
                               stats1, gamma1, beta1, invM);
    {
        dim3 grid(H2 / GBN, (N + GBM - 1) / GBM);
        k_gemm_h<<<grid, 256, SMEM_H>>>(agg2h, w2t, b2, h2, stats2, N, H2, H1);
    }

    {
        dim3 grid(DOUT / GBN, (N + GBM - 1) / GBM);
        k_gemm_finh<<<grid, 256, SMEM_FINH>>>(h2, wlt, bl, out,
                                              stats2, gamma2, beta2, invM,
                                              N, DOUT, H2);
    }
}

// round 16
// speedup vs baseline: 1.0790x; 1.0790x over previous
#include <cuda_runtime.h>
#include <cuda_bf16.h>
#include <cuda_fp16.h>
#include <cstdint>

// ---------------------------------------------------------------------------
// GCN encoder: N=50000, E=500000, 128 -> 256 -> 512 -> 128
// R7 configuration (session best, 270.8us): CSR gather aggregation (BN fused,
// fp16 activations) + fp16 mma.sync tensor-core GEMM pipelines (128x128,
// 2-stage cp.async) with fused BN stats + separate tiny bnprep kernels.
// ---------------------------------------------------------------------------

#define MAXN 50048
#define MAXE 524288
#define EPS 1e-5f
#define SCAN_BLK 1024

__device__ float  g_dinv[MAXN];
__device__ int    g_cnt[MAXN];
__device__ int    g_rowptr[MAXN + 1];
__device__ int    g_cursor[MAXN];
__device__ int    g_bsum[64];
__device__ int2   g_adj[MAXE];                 // (src, bits(w))
__device__ __half g_agg1h[(size_t)MAXN * 128];
__device__ __half g_agg2h[(size_t)MAXN * 256];
__device__ __half g_h1[(size_t)MAXN * 256];    // fp16 raw (pre-BN)
__device__ __half g_h2[(size_t)MAXN * 512];
__device__ __half g_w1t[256 * 128];            // fp16 W1^T [N][K]
__device__ __half g_w2t[512 * 256];
__device__ __half g_wlt[128 * 512];
__device__ float2 g_stats1[256];
__device__ float2 g_stats2[512];
__device__ float2 g_ss1[256];
__device__ float2 g_ss2[512];
__device__ int    g_flag32;

// ---------------------------------------------------------------------------

__device__ __forceinline__ void red_add_v2(float2* addr, float a, float b) {
    asm volatile("red.global.add.v2.f32 [%0], {%1,%2};"
                 :: "l"(addr), "f"(a), "f"(b) : "memory");
}

__device__ __forceinline__ int load_idx(const void* ei, long long pos, int is32) {
    if (is32) return ((const int*)ei)[pos];
    return (int)(((const long long*)ei)[pos]);
}

__device__ __forceinline__ uint32_t pack_h2(float lo, float hi) {
    uint32_t u;
    asm("cvt.rn.f16x2.f32 %0, %1, %2;" : "=r"(u) : "f"(hi), "f"(lo));
    return u;
}

__device__ __forceinline__ float2 unpack_h2(uint32_t u) {
    __half2 h = *(__half2*)&u;
    return __half22float2(h);
}

__device__ __forceinline__ void cp_async16(void* sptr, const void* gptr, int src_bytes) {
    uint32_t sa = (uint32_t)__cvta_generic_to_shared(sptr);
    asm volatile("cp.async.cg.shared.global [%0], [%1], 16, %2;"
                 :: "r"(sa), "l"(gptr), "r"(src_bytes));
}

// --- prep0 (+fused dtype detect on block 0): zero cnt + stats ----------------
__global__ void k_prep0(const int* __restrict__ ei32, long long E,
                        int* cnt, int n, float2* st1, float2* st2,
                        int d1, int d2, int* flag) {
    int i = blockIdx.x * blockDim.x + threadIdx.x;
    if (blockIdx.x == 0) {
        long long lim = E < 8192 ? E : 8192;
        int any = 0;
        for (long long j = threadIdx.x; j < lim; j += blockDim.x)
            if (ei32[2 * j + 1] != 0) any = 1;
        if (any) atomicOr(flag, 1);
    }
    if (i < n) cnt[i] = 0;
    if (i < d1) st1[i] = make_float2(0.f, 0.f);
    if (i < d2) st2[i] = make_float2(0.f, 0.f);
}

// --- in-degree counts ---------------------------------------------------------
__global__ void k_count(const void* ei, long long E, const int* flag, int* cnt) {
    long long i = blockIdx.x * (long long)blockDim.x + threadIdx.x;
    long long stride = (long long)gridDim.x * blockDim.x;
    int is32 = *flag;
    for (; i < E; i += stride) {
        int d = load_idx(ei, E + i, is32);
        atomicAdd(&cnt[d], 1);
    }
}

// --- scan pass 1: per-block sums -----------------------------------------------
__global__ __launch_bounds__(SCAN_BLK) void k_scan_red(const int* __restrict__ cnt,
                                                       int* __restrict__ bsum, int n) {
    int i = blockIdx.x * SCAN_BLK + threadIdx.x;
    int v = (i < n) ? cnt[i] : 0;
    int lane = threadIdx.x & 31, wid = threadIdx.x >> 5;
#pragma unroll
    for (int off = 16; off; off >>= 1) v += __shfl_xor_sync(0xffffffffu, v, off);
    __shared__ int ws[32];
    if (lane == 0) ws[wid] = v;
    __syncthreads();
    if (wid == 0) {
        v = ws[lane];
#pragma unroll
        for (int off = 16; off; off >>= 1) v += __shfl_xor_sync(0xffffffffu, v, off);
        if (lane == 0) bsum[blockIdx.x] = v;
    }
}

// --- scan pass 2: block offset + local scan + apply -----------------------------
__global__ __launch_bounds__(SCAN_BLK) void k_scan_apply(const int* __restrict__ cnt,
                                                         const int* __restrict__ bsum, int nb,
                                                         int* __restrict__ rowptr,
                                                         int* __restrict__ cursor,
                                                         float* __restrict__ dinv, int n) {
    int tid = threadIdx.x;
    int lane = tid & 31, wid = tid >> 5;
    __shared__ int ws[32];
    __shared__ int s_off;

    int b = (tid < nb && tid < blockIdx.x) ? bsum[tid] : 0;
#pragma unroll
    for (int off = 16; off; off >>= 1) b += __shfl_xor_sync(0xffffffffu, b, off);
    if (lane == 0) ws[wid] = b;
    __syncthreads();
    if (wid == 0) {
        int w = ws[lane];
#pragma unroll
        for (int off = 16; off; off >>= 1) w += __shfl_xor_sync(0xffffffffu, w, off);
        if (lane == 0) s_off = w;
    }
    __syncthreads();
    int offset = s_off;
    __syncthreads();

    int i = blockIdx.x * SCAN_BLK + tid;
    int v = (i < n) ? cnt[i] : 0;
    int x = v;
#pragma unroll
    for (int off = 1; off < 32; off <<= 1) {
        int y = __shfl_up_sync(0xffffffffu, x, off);
        if (lane >= off) x += y;
    }
    if (lane == 31) ws[wid] = x;
    __syncthreads();
    if (wid == 0) {
        int w = ws[lane];
#pragma unroll
        for (int off = 1; off < 32; off <<= 1) {
            int y = __shfl_up_sync(0xffffffffu, w, off);
            if (lane >= off) w += y;
        }
        ws[lane] = w;
    }
    __syncthreads();
    int incl = x + (wid > 0 ? ws[wid - 1] : 0);
    int excl = incl - v + offset;
    if (i < n) {
        rowptr[i] = excl;
        cursor[i] = excl;
        dinv[i] = rsqrtf((float)v + 1.0f);
        if (i == n - 1) rowptr[n] = excl + v;
    }
}

// --- bucket-fill adjacency -------------------------------------------------------
__global__ void k_fill(const void* __restrict__ ei, long long E, const int* flag,
                       const float* __restrict__ dinv, int* __restrict__ cursor,
                       int2* __restrict__ adj) {
    long long i = blockIdx.x * (long long)blockDim.x + threadIdx.x;
    long long stride = (long long)gridDim.x * blockDim.x;
    int is32 = *flag;
    for (; i < E; i += stride) {
        int s = load_idx(ei, i, is32);
        int d = load_idx(ei, E + i, is32);
        float w = dinv[s] * dinv[d];
        int pos = atomicAdd(&cursor[d], 1);
        adj[pos] = make_int2(s, __float_as_int(w));
    }
}

// --- weight convert: all three -> fp16 transposed [N][K] --------------------------
__global__ void k_cvtw(const float* __restrict__ W1, const float* __restrict__ W2,
                       const float* __restrict__ W3,
                       __half* __restrict__ t1, __half* __restrict__ t2,
                       __half* __restrict__ t3,
                       int K1, int N1, int K2, int N2, int K3, int N3) {
    int i = blockIdx.x * blockDim.x + threadIdx.x;
    if (i < K1 * N1) {
        int k = i / N1, n = i % N1;
        t1[n * K1 + k] = __float2half_rn(W1[i]);
    }
    if (i < K2 * N2) {
        int k = i / N2, n = i % N2;
        t2[n * K2 + k] = __float2half_rn(W2[i]);
    }
    if (i < K3 * N3) {
        int k = i / N3, n = i % N3;
        t3[n * K3 + k] = __float2half_rn(W3[i]);
    }
}

// --- agg layer 1: fp32 x in, fp16 out ----------------------------------------------
__global__ __launch_bounds__(256) void k_agg1(const int2* __restrict__ adj,
                                              const int* __restrict__ rowptr,
                                              const float* __restrict__ dinv,
                                              const float* __restrict__ X,
                                              __half* __restrict__ out, int N) {
    int node = (blockIdx.x * blockDim.x + threadIdx.x) >> 5;
    int lane = threadIdx.x & 31;
    if (node >= N) return;
    float w0 = dinv[node]; w0 *= w0;
    float4 a = ((const float4*)(X + (size_t)node * 128))[lane];
    float4 acc = make_float4(a.x * w0, a.y * w0, a.z * w0, a.w * w0);
    int j = rowptr[node], end = rowptr[node + 1];
    int2 e = (j < end) ? adj[j] : make_int2(0, 0);
    for (; j < end; j++) {
        int2 cur = e;
        if (j + 1 < end) e = adj[j + 1];
        float w = __int_as_float(cur.y);
        float4 s = ((const float4*)(X + (size_t)cur.x * 128))[lane];
        acc.x += w * s.x; acc.y += w * s.y;
        acc.z += w * s.z; acc.w += w * s.w;
    }
    ((uint2*)(out + (size_t)node * 128))[lane] =
        make_uint2(pack_h2(acc.x, acc.y), pack_h2(acc.z, acc.w));
}

// --- agg layer 2: fp16 h1 in (BN+ReLU fused via precomputed ss), fp16 out ---------
__global__ __launch_bounds__(256) void k_agg2(const int2* __restrict__ adj,
                                              const int* __restrict__ rowptr,
                                              const float* __restrict__ dinv,
                                              const __half* __restrict__ X,
                                              __half* __restrict__ out, int N,
                                              const float2* __restrict__ ss) {
    int node = (blockIdx.x * blockDim.x + threadIdx.x) >> 5;
    int lane = threadIdx.x & 31;
    if (node >= N) return;
    float2 sr[8];
#pragma unroll
    for (int j = 0; j < 8; j++) sr[j] = ss[lane * 8 + j];

    float acc[8];
    float w0 = dinv[node]; w0 *= w0;
    {
        uint4 u = ((const uint4*)(X + (size_t)node * 256))[lane];
        float2 f0 = unpack_h2(u.x), f1 = unpack_h2(u.y);
        float2 f2 = unpack_h2(u.z), f3 = unpack_h2(u.w);
        float f[8] = {f0.x, f0.y, f1.x, f1.y, f2.x, f2.y, f3.x, f3.y};
#pragma unroll
        for (int j = 0; j < 8; j++)
            acc[j] = w0 * fmaxf(fmaf(f[j], sr[j].x, sr[j].y), 0.f);
    }
    int j = rowptr[node], end = rowptr[node + 1];
    int2 e = (j < end) ? adj[j] : make_int2(0, 0);
    for (; j < end; j++) {
        int2 cur = e;
        if (j + 1 < end) e = adj[j + 1];
        float w = __int_as_float(cur.y);
        uint4 u = ((const uint4*)(X + (size_t)cur.x * 256))[lane];
        float2 f0 = unpack_h2(u.x), f1 = unpack_h2(u.y);
        float2 f2 = unpack_h2(u.z), f3 = unpack_h2(u.w);
        float f[8] = {f0.x, f0.y, f1.x, f1.y, f2.x, f2.y, f3.x, f3.y};
#pragma unroll
        for (int jj = 0; jj < 8; jj++)
            acc[jj] += w * fmaxf(fmaf(f[jj], sr[jj].x, sr[jj].y), 0.f);
    }
    uint4 o;
    o.x = pack_h2(acc[0], acc[1]);
    o.y = pack_h2(acc[2], acc[3]);
    o.z = pack_h2(acc[4], acc[5]);
    o.w = pack_h2(acc[6], acc[7]);
    ((uint4*)(out + (size_t)node * 256))[lane] = o;
}

// ---------------------------------------------------------------------------
// fp16 mma.sync pipelined GEMM: 128x128 tile, 8 warps (32x64), BK=32,
// cp.async 2-stage. Fused bias + fp32 BN stats, fp16 C.
// ---------------------------------------------------------------------------
#define GBM 128
#define GBN 128
#define HASTR 40
#define HTSZ (128 * HASTR)
#define SMEM_H ((4 * HTSZ) * 2)
#define SMEM_FINH (SMEM_H + 512 * 8)

__global__ __launch_bounds__(256) void k_gemm_h(const __half* __restrict__ A,
                                                const __half* __restrict__ Bt,
                                                const float* __restrict__ bias,
                                                __half* __restrict__ C,
                                                float2* __restrict__ stats,
                                                int M, int N, int K) {
    extern __shared__ __half smh[];
    __half* As = smh;
    __half* Bs = smh + 2 * HTSZ;

    const int tid  = threadIdx.x;
    const int lane = tid & 31;
    const int warpId = tid >> 5;
    const int warpM = warpId & 3;
    const int warpN = warpId >> 2;
    const int g = lane >> 2;
    const int t = lane & 3;
    const int bm = blockIdx.y * GBM;
    const int bn = blockIdx.x * GBN;

    const int l_row = tid >> 2;
    const int l_chk = (tid & 3) * 8;

    float4 acc[2][8];
#pragma unroll
    for (int i = 0; i < 2; i++)
#pragma unroll
        for (int j = 0; j < 8; j++)
            acc[i][j] = make_float4(0.f, 0.f, 0.f, 0.f);

    auto load_stage = [&](int stg, int k0) {
        __half* pa = As + stg * HTSZ;
        __half* pb = Bs + stg * HTSZ;
#pragma unroll
        for (int i = 0; i < 2; i++) {
            int row = i * 64 + l_row;
            int gm = bm + row;
            int ok = (gm < M) ? 16 : 0;
            int gmc = min(gm, M - 1);
            cp_async16(pa + row * HASTR + l_chk, A + (size_t)gmc * K + k0 + l_chk, ok);
        }
#pragma unroll
        for (int i = 0; i < 2; i++) {
            int row = i * 64 + l_row;
            cp_async16(pb + row * HASTR + l_chk, Bt + (size_t)(bn + row) * K + k0 + l_chk, 16);
        }
    };

    const int nk = K / 32;
    load_stage(0, 0);
    asm volatile("cp.async.commit_group;");

    for (int tk = 0; tk < nk; tk++) {
        if (tk + 1 < nk) {
            load_stage((tk + 1) & 1, (tk + 1) * 32);
            asm volatile("cp.async.commit_group;");
            asm volatile("cp.async.wait_group 1;");
        } else {
            asm volatile("cp.async.wait_group 0;");
        }
        __syncthreads();

        const __half* pa = As + (tk & 1) * HTSZ;
        const __half* pb = Bs + (tk & 1) * HTSZ;
#pragma unroll
        for (int kk = 0; kk < 32; kk += 16) {
            uint32_t afrag[2][4];
            uint32_t bfrag[8][2];
#pragma unroll
            for (int im = 0; im < 2; im++) {
                const __half* base = pa + (warpM * 32 + im * 16 + g) * HASTR + kk + 2 * t;
                afrag[im][0] = *(const uint32_t*)(base);
                afrag[im][1] = *(const uint32_t*)(base + 8 * HASTR);
                afrag[im][2] = *(const uint32_t*)(base + 8);
                afrag[im][3] = *(const uint32_t*)(base + 8 * HASTR + 8);
            }
#pragma unroll
            for (int jn = 0; jn < 8; jn++) {
                const __half* base = pb + (warpN * 64 + jn * 8 + g) * HASTR + kk + 2 * t;
                bfrag[jn][0] = *(const uint32_t*)(base);
                bfrag[jn][1] = *(const uint32_t*)(base + 8);
            }
#pragma unroll
            for (int im = 0; im < 2; im++)
#pragma unroll
                for (int jn = 0; jn < 8; jn++) {
                    float4& c = acc[im][jn];
                    asm volatile(
                        "mma.sync.aligned.m16n8k16.row.col.f32.f16.f16.f32 "
                        "{%0,%1,%2,%3}, {%4,%5,%6,%7}, {%8,%9}, {%0,%1,%2,%3};"
                        : "+f"(c.x), "+f"(c.y), "+f"(c.z), "+f"(c.w)
                        : "r"(afrag[im][0]), "r"(afrag[im][1]),
                          "r"(afrag[im][2]), "r"(afrag[im][3]),
                          "r"(bfrag[jn][0]), "r"(bfrag[jn][1]));
                }
        }
        __syncthreads();
    }

#pragma unroll
    for (int jn = 0; jn < 8; jn++) {
        int col = bn + warpN * 64 + jn * 8 + 2 * t;
        float bx = bias[col], by = bias[col + 1];
        float s0 = 0.f, q0 = 0.f, s1 = 0.f, q1 = 0.f;
#pragma unroll
        for (int im = 0; im < 2; im++) {
            int row0 = bm + warpM * 32 + im * 16 + g;
            float4 c = acc[im][jn];
            if (row0 < M) {
                float ox = c.x + bx, oy = c.y + by;
                *(uint32_t*)(C + (size_t)row0 * N + col) = pack_h2(ox, oy);
                s0 += ox; q0 += ox * ox; s1 += oy; q1 += oy * oy;
            }
            if (row0 + 8 < M) {
                float oz = c.z + bx, ow = c.w + by;
                *(uint32_t*)(C + (size_t)(row0 + 8) * N + col) = pack_h2(oz, ow);
                s0 += oz; q0 += oz * oz; s1 += ow; q1 += ow * ow;
            }
        }
#pragma unroll
        for (int m = 4; m < 32; m <<= 1) {
            s0 += __shfl_xor_sync(0xffffffffu, s0, m);
            q0 += __shfl_xor_sync(0xffffffffu, q0, m);
            s1 += __shfl_xor_sync(0xffffffffu, s1, m);
            q1 += __shfl_xor_sync(0xffffffffu, q1, m);
        }
        if (g == 0) {
            red_add_v2(&stats[col], s0, q0);
            red_add_v2(&stats[col + 1], s1, q1);
        }
    }
}

// ---------------------------------------------------------------------------
// Final fp16 GEMM: A = raw fp16 h2, BN2+ReLU applied at frag build from
// precomputed ss (staged to smem), B = fp16 Wl^T. fp32 out.
// ---------------------------------------------------------------------------
__global__ __launch_bounds__(256) void k_gemm_finh(const __half* __restrict__ A,
                                                   const __half* __restrict__ Bt,
                                                   const float* __restrict__ bias,
                                                   float* __restrict__ C,
                                                   const float2* __restrict__ ssA,
                                                   int M, int N, int K) {
    extern __shared__ __half smh[];
    __half* As = smh;
    __half* Bs = smh + 2 * HTSZ;
    float2* ssm = (float2*)(smh + 4 * HTSZ);

    const int tid  = threadIdx.x;
    const int lane = tid & 31;
    const int warpId = tid >> 5;
    const int warpM = warpId & 3;
    const int warpN = warpId >> 2;
    const int g = lane >> 2;
    const int t = lane & 3;
    const int bm = blockIdx.y * GBM;
    const int bn = blockIdx.x * GBN;

    for (int c = tid; c < K; c += 256) ssm[c] = ssA[c];

    const int l_row = tid >> 2;
    const int l_chk = (tid & 3) * 8;

    float4 acc[2][8];
#pragma unroll
    for (int i = 0; i < 2; i++)
#pragma unroll
        for (int j = 0; j < 8; j++)
            acc[i][j] = make_float4(0.f, 0.f, 0.f, 0.f);

    auto load_stage = [&](int stg, int k0) {
        __half* pa = As + stg * HTSZ;
        __half* pb = Bs + stg * HTSZ;
#pragma unroll
        for (int i = 0; i < 2; i++) {
            int row = i * 64 + l_row;
            int gm = bm + row;
            int ok = (gm < M) ? 16 : 0;
            int gmc = min(gm, M - 1);
            cp_async16(pa + row * HASTR + l_chk, A + (size_t)gmc * K + k0 + l_chk, ok);
        }
#pragma unroll
        for (int i = 0; i < 2; i++) {
            int row = i * 64 + l_row;
            cp_async16(pb + row * HASTR + l_chk, Bt + (size_t)(bn + row) * K + k0 + l_chk, 16);
        }
    };

    const int nk = K / 32;
    load_stage(0, 0);
    asm volatile("cp.async.commit_group;");

    for (int tk = 0; tk < nk; tk++) {
        if (tk + 1 < nk) {
            load_stage((tk + 1) & 1, (tk + 1) * 32);
            asm volatile("cp.async.commit_group;");
            asm volatile("cp.async.wait_group 1;");
        } else {
            asm volatile("cp.async.wait_group 0;");
        }
        __syncthreads();

        const __half* pa = As + (tk & 1) * HTSZ;
        const __half* pb = Bs + (tk & 1) * HTSZ;
        const int kbase = tk * 32;
#pragma unroll
        for (int kk = 0; kk < 32; kk += 16) {
            int kc = kbase + kk + 2 * t;
            float2 s0 = ssm[kc],     s1 = ssm[kc + 1];
            float2 s2 = ssm[kc + 8], s3 = ssm[kc + 9];
            uint32_t afrag[2][4];
            uint32_t bfrag[8][2];
#pragma unroll
            for (int im = 0; im < 2; im++) {
                const __half* base = pa + (warpM * 32 + im * 16 + g) * HASTR + kk + 2 * t;
                float2 f0 = unpack_h2(*(const uint32_t*)(base));
                float2 f1 = unpack_h2(*(const uint32_t*)(base + 8 * HASTR));
                float2 f2 = unpack_h2(*(const uint32_t*)(base + 8));
                float2 f3 = unpack_h2(*(const uint32_t*)(base + 8 * HASTR + 8));
                afrag[im][0] = pack_h2(fmaxf(fmaf(f0.x, s0.x, s0.y), 0.f),
                                       fmaxf(fmaf(f0.y, s1.x, s1.y), 0.f));
                afrag[im][1] = pack_h2(fmaxf(fmaf(f1.x, s0.x, s0.y), 0.f),
                                       fmaxf(fmaf(f1.y, s1.x, s1.y), 0.f));
                afrag[im][2] = pack_h2(fmaxf(fmaf(f2.x, s2.x, s2.y), 0.f),
                                       fmaxf(fmaf(f2.y, s3.x, s3.y), 0.f));
                afrag[im][3] = pack_h2(fmaxf(fmaf(f3.x, s2.x, s2.y), 0.f),
                                       fmaxf(fmaf(f3.y, s3.x, s3.y), 0.f));
            }
#pragma unroll
            for (int jn = 0; jn < 8; jn++) {
                const __half* base = pb + (warpN * 64 + jn * 8 + g) * HASTR + kk + 2 * t;
                bfrag[jn][0] = *(const uint32_t*)(base);
                bfrag[jn][1] = *(const uint32_t*)(base + 8);
            }
#pragma unroll
            for (int im = 0; im < 2; im++)
#pragma unroll
                for (int jn = 0; jn < 8; jn++) {
                    float4& c = acc[im][jn];
                    asm volatile(
                        "mma.sync.aligned.m16n8k16.row.col.f32.f16.f16.f32 "
                        "{%0,%1,%2,%3}, {%4,%5,%6,%7}, {%8,%9}, {%0,%1,%2,%3};"
                        : "+f"(c.x), "+f"(c.y), "+f"(c.z), "+f"(c.w)
                        : "r"(afrag[im][0]), "r"(afrag[im][1]),
                          "r"(afrag[im][2]), "r"(afrag[im][3]),
                          "r"(bfrag[jn][0]), "r"(bfrag[jn][1]));
                }
        }
        __syncthreads();
    }

#pragma unroll
    for (int jn = 0; jn < 8; jn++) {
        int col = bn + warpN * 64 + jn * 8 + 2 * t;
        float bx = bias[col], by = bias[col + 1];
#pragma unroll
        for (int im = 0; im < 2; im++) {
            int row0 = bm + warpM * 32 + im * 16 + g;
            float4 c = acc[im][jn];
            if (row0 < M)
                *(float2*)(C + (size_t)row0 * N + col) = make_float2(c.x + bx, c.y + by);
            if (row0 + 8 < M)
                *(float2*)(C + (size_t)(row0 + 8) * N + col) = make_float2(c.z + bx, c.w + by);
        }
    }
}

// --- stats -> per-col (scale, shift) ------------------------------------------
__global__ void k_bnprep(const float2* __restrict__ stats,
                         const float* __restrict__ gamma,
                         const float* __restrict__ beta,
                         float2* __restrict__ ss, int D, float invM) {
    int c = blockIdx.x * blockDim.x + threadIdx.x;
    if (c < D) {
        float mu = stats[c].x * invM;
        float var = stats[c].y * invM - mu * mu;
        float sc = gamma[c] * rsqrtf(var + EPS);
        ss[c] = make_float2(sc, beta[c] - mu * sc);
    }
}

// ---------------------------------------------------------------------------

extern "C" void kernel_launch(void* const* d_in, const int* in_sizes, int n_in,
                              void* d_out, int out_size) {
    const float* x      = (const float*)d_in[0];
    const void*  ei     = d_in[1];
    const float* W1     = (const float*)d_in[2];
    const float* b1     = (const float*)d_in[3];
    const float* gamma1 = (const float*)d_in[4];
    const float* beta1  = (const float*)d_in[5];
    const float* W2     = (const float*)d_in[6];
    const float* b2     = (const float*)d_in[7];
    const float* gamma2 = (const float*)d_in[8];
    const float* beta2  = (const float*)d_in[9];
    const float* Wl     = (const float*)d_in[10];
    const float* bl     = (const float*)d_in[11];

    const int H1   = in_sizes[3];
    const int H2   = in_sizes[7];
    const int DOUT = in_sizes[11];
    const int DIN  = in_sizes[2] / H1;
    const int N    = in_sizes[0] / DIN;
    const long long E = in_sizes[1] / 2;
    const float invM = 1.0f / (float)N;

    float *dinv;
    __half *agg1h, *agg2h, *h1, *h2, *w1t, *w2t, *wlt;
    float2 *stats1, *stats2, *ss1, *ss2;
    int *cnt, *rowptr, *cursor, *flag, *bsum;
    int2* adj;
    cudaGetSymbolAddress((void**)&dinv,   g_dinv);
    cudaGetSymbolAddress((void**)&cnt,    g_cnt);
    cudaGetSymbolAddress((void**)&rowptr, g_rowptr);
    cudaGetSymbolAddress((void**)&cursor, g_cursor);
    cudaGetSymbolAddress((void**)&bsum,   g_bsum);
    cudaGetSymbolAddress((void**)&adj,    g_adj);
    cudaGetSymbolAddress((void**)&agg1h,  g_agg1h);
    cudaGetSymbolAddress((void**)&agg2h,  g_agg2h);
    cudaGetSymbolAddress((void**)&h1,     g_h1);
    cudaGetSymbolAddress((void**)&h2,     g_h2);
    cudaGetSymbolAddress((void**)&w1t,    g_w1t);
    cudaGetSymbolAddress((void**)&w2t,    g_w2t);
    cudaGetSymbolAddress((void**)&wlt,    g_wlt);
    cudaGetSymbolAddress((void**)&stats1, g_stats1);
    cudaGetSymbolAddress((void**)&stats2, g_stats2);
    cudaGetSymbolAddress((void**)&ss1,    g_ss1);
    cudaGetSymbolAddress((void**)&ss2,    g_ss2);
    cudaGetSymbolAddress((void**)&flag,   g_flag32);

    float* out = (float*)d_out;

    cudaFuncSetAttribute(k_gemm_h,    cudaFuncAttributeMaxDynamicSharedMemorySize, SMEM_H);
    cudaFuncSetAttribute(k_gemm_finh, cudaFuncAttributeMaxDynamicSharedMemorySize, SMEM_FINH);

    const int scanBlocks = (N + SCAN_BLK - 1) / SCAN_BLK;
    const int aggBlocks = (int)(((long long)N * 32 + 255) / 256);

    // prep (5 launches)
    k_prep0<<<(N + 255) / 256, 256>>>((const int*)ei, E, cnt, N, stats1, stats2, H1, H2, flag);
    k_count<<<1024, 256>>>(ei, E, flag, cnt);
    k_scan_red<<<scanBlocks, SCAN_BLK>>>(cnt, bsum, N);
    k_scan_apply<<<scanBlocks, SCAN_BLK>>>(cnt, bsum, scanBlocks, rowptr, cursor, dinv, N);
    k_fill<<<1024, 256>>>(ei, E, flag, dinv, cursor, adj);

    // layer 1
    k_agg1<<<aggBlocks, 256>>>(adj, rowptr, dinv, x, agg1h, N);
    k_cvtw<<<(H1 * H2 + 255) / 256, 256>>>(W1, W2, Wl, w1t, w2t, wlt,
                                           DIN, H1, H1, H2, H2, DOUT);
    {
        dim3 grid(H1 / GBN, (N + GBM - 1) / GBM);
        k_gemm_h<<<grid, 256, SMEM_H>>>(agg1h, w1t, b1, h1, stats1, N, H1, DIN);
        k_bnprep<<<(H1 + 255) / 256, 256>>>(stats1, gamma1, beta1, ss1, H1, invM);
    }

    // layer 2
    k_agg2<<<aggBlocks, 256>>>(adj, rowptr, dinv, h1, agg2h, N, ss1);
    {
        dim3 grid(H2 / GBN, (N + GBM - 1) / GBM);
        k_gemm_h<<<grid, 256, SMEM_H>>>(agg2h, w2t, b2, h2, stats2, N, H2, H1);
        k_bnprep<<<(H2 + 255) / 256, 256>>>(stats2, gamma2, beta2, ss2, H2, invM);
    }

    // final projection
    {
        dim3 grid(DOUT / GBN, (N + GBM - 1) / GBM);
        k_gemm_finh<<<grid, 256, SMEM_FINH>>>(h2, wlt, bl, out, ss2, N, DOUT, H2);
    }
}

// round 17
// speedup vs baseline: 1.0955x; 1.0152x over previous
#include <cuda_runtime.h>
#include <cuda_bf16.h>
#include <cuda_fp16.h>
#include <cstdint>

// ---------------------------------------------------------------------------
// GCN encoder: N=50000, E=500000, 128 -> 256 -> 512 -> 128
// R7 core (session best, reproduced 270.8us) with launch-count reduction:
//  - bnprep done by the LAST CTA of each k_gemm_h (threadfence-reduction)
//  - agg1 and cvtw fused into one kernel via block partition
// 10 launches total; all inner loops byte-identical to R7.
// ---------------------------------------------------------------------------

#define MAXN 50048
#define MAXE 524288
#define EPS 1e-5f
#define SCAN_BLK 1024

__device__ float  g_dinv[MAXN];
__device__ int    g_cnt[MAXN];
__device__ int    g_rowptr[MAXN + 1];
__device__ int    g_cursor[MAXN];
__device__ int    g_bsum[64];
__device__ int2   g_adj[MAXE];                 // (src, bits(w))
__device__ __half g_agg1h[(size_t)MAXN * 128];
__device__ __half g_agg2h[(size_t)MAXN * 256];
__device__ __half g_h1[(size_t)MAXN * 256];    // fp16 raw (pre-BN)
__device__ __half g_h2[(size_t)MAXN * 512];
__device__ __half g_w1t[256 * 128];            // fp16 W1^T [N][K]
__device__ __half g_w2t[512 * 256];
__device__ __half g_wlt[128 * 512];
__device__ float2 g_stats1[256];
__device__ float2 g_stats2[512];
__device__ float2 g_ss1[256];
__device__ float2 g_ss2[512];
__device__ int    g_flag32;
__device__ int    g_done;                      // last-CTA counter (zero-init; reset each use)

// ---------------------------------------------------------------------------

__device__ __forceinline__ void red_add_v2(float2* addr, float a, float b) {
    asm volatile("red.global.add.v2.f32 [%0], {%1,%2};"
                 :: "l"(addr), "f"(a), "f"(b) : "memory");
}

__device__ __forceinline__ int load_idx(const void* ei, long long pos, int is32) {
    if (is32) return ((const int*)ei)[pos];
    return (int)(((const long long*)ei)[pos]);
}

__device__ __forceinline__ uint32_t pack_h2(float lo, float hi) {
    uint32_t u;
    asm("cvt.rn.f16x2.f32 %0, %1, %2;" : "=r"(u) : "f"(hi), "f"(lo));
    return u;
}

__device__ __forceinline__ float2 unpack_h2(uint32_t u) {
    __half2 h = *(__half2*)&u;
    return __half22float2(h);
}

__device__ __forceinline__ void cp_async16(void* sptr, const void* gptr, int src_bytes) {
    uint32_t sa = (uint32_t)__cvta_generic_to_shared(sptr);
    asm volatile("cp.async.cg.shared.global [%0], [%1], 16, %2;"
                 :: "r"(sa), "l"(gptr), "r"(src_bytes));
}

// BN (scale, shift) from raw stats — identical fp32 ops as the old k_bnprep
__device__ __forceinline__ float2 bn_ss(float2 st, float gamma, float beta, float invM) {
    float mu = st.x * invM;
    float var = st.y * invM - mu * mu;
    float sc = gamma * rsqrtf(var + EPS);
    return make_float2(sc, beta - mu * sc);
}

// --- prep0 (+fused dtype detect on block 0): zero cnt + stats ----------------
__global__ void k_prep0(const int* __restrict__ ei32, long long E,
                        int* cnt, int n, float2* st1, float2* st2,
                        int d1, int d2, int* flag) {
    int i = blockIdx.x * blockDim.x + threadIdx.x;
    if (blockIdx.x == 0) {
        long long lim = E < 8192 ? E : 8192;
        int any = 0;
        for (long long j = threadIdx.x; j < lim; j += blockDim.x)
            if (ei32[2 * j + 1] != 0) any = 1;
        if (any) atomicOr(flag, 1);
    }
    if (i < n) cnt[i] = 0;
    if (i < d1) st1[i] = make_float2(0.f, 0.f);
    if (i < d2) st2[i] = make_float2(0.f, 0.f);
}

// --- in-degree counts ---------------------------------------------------------
__global__ void k_count(const void* ei, long long E, const int* flag, int* cnt) {
    long long i = blockIdx.x * (long long)blockDim.x + threadIdx.x;
    long long stride = (long long)gridDim.x * blockDim.x;
    int is32 = *flag;
    for (; i < E; i += stride) {
        int d = load_idx(ei, E + i, is32);
        atomicAdd(&cnt[d], 1);
    }
}

// --- scan pass 1: per-block sums -----------------------------------------------
__global__ __launch_bounds__(SCAN_BLK) void k_scan_red(const int* __restrict__ cnt,
                                                       int* __restrict__ bsum, int n) {
    int i = blockIdx.x * SCAN_BLK + threadIdx.x;
    int v = (i < n) ? cnt[i] : 0;
    int lane = threadIdx.x & 31, wid = threadIdx.x >> 5;
#pragma unroll
    for (int off = 16; off; off >>= 1) v += __shfl_xor_sync(0xffffffffu, v, off);
    __shared__ int ws[32];
    if (lane == 0) ws[wid] = v;
    __syncthreads();
    if (wid == 0) {
        v = ws[lane];
#pragma unroll
        for (int off = 16; off; off >>= 1) v += __shfl_xor_sync(0xffffffffu, v, off);
        if (lane == 0) bsum[blockIdx.x] = v;
    }
}

// --- scan pass 2: block offset + local scan + apply -----------------------------
__global__ __launch_bounds__(SCAN_BLK) void k_scan_apply(const int* __restrict__ cnt,
                                                         const int* __restrict__ bsum, int nb,
                                                         int* __restrict__ rowptr,
                                                         int* __restrict__ cursor,
                                                         float* __restrict__ dinv, int n) {
    int tid = threadIdx.x;
    int lane = tid & 31, wid = tid >> 5;
    __shared__ int ws[32];
    __shared__ int s_off;

    int b = (tid < nb && tid < blockIdx.x) ? bsum[tid] : 0;
#pragma unroll
    for (int off = 16; off; off >>= 1) b += __shfl_xor_sync(0xffffffffu, b, off);
    if (lane == 0) ws[wid] = b;
    __syncthreads();
    if (wid == 0) {
        int w = ws[lane];
#pragma unroll
        for (int off = 16; off; off >>= 1) w += __shfl_xor_sync(0xffffffffu, w, off);
        if (lane == 0) s_off = w;
    }
    __syncthreads();
    int offset = s_off;
    __syncthreads();

    int i = blockIdx.x * SCAN_BLK + tid;
    int v = (i < n) ? cnt[i] : 0;
    int x = v;
#pragma unroll
    for (int off = 1; off < 32; off <<= 1) {
        int y = __shfl_up_sync(0xffffffffu, x, off);
        if (lane >= off) x += y;
    }
    if (lane == 31) ws[wid] = x;
    __syncthreads();
    if (wid == 0) {
        int w = ws[lane];
#pragma unroll
        for (int off = 1; off < 32; off <<= 1) {
            int y = __shfl_up_sync(0xffffffffu, w, off);
            if (lane >= off) w += y;
        }
        ws[lane] = w;
    }
    __syncthreads();
    int incl = x + (wid > 0 ? ws[wid - 1] : 0);
    int excl = incl - v + offset;
    if (i < n) {
        rowptr[i] = excl;
        cursor[i] = excl;
        dinv[i] = rsqrtf((float)v + 1.0f);
        if (i == n - 1) rowptr[n] = excl + v;
    }
}

// --- bucket-fill adjacency -------------------------------------------------------
__global__ void k_fill(const void* __restrict__ ei, long long E, const int* flag,
                       const float* __restrict__ dinv, int* __restrict__ cursor,
                       int2* __restrict__ adj) {
    long long i = blockIdx.x * (long long)blockDim.x + threadIdx.x;
    long long stride = (long long)gridDim.x * blockDim.x;
    int is32 = *flag;
    for (; i < E; i += stride) {
        int s = load_idx(ei, i, is32);
        int d = load_idx(ei, E + i, is32);
        float w = dinv[s] * dinv[d];
        int pos = atomicAdd(&cursor[d], 1);
        adj[pos] = make_int2(s, __float_as_int(w));
    }
}

// --- agg layer 1 (blocks [0, aggBlocks)) + weight cvt (rest) — fused ---------------
__global__ __launch_bounds__(256) void k_agg1w(const int2* __restrict__ adj,
                                               const int* __restrict__ rowptr,
                                               const float* __restrict__ dinv,
                                               const float* __restrict__ X,
                                               __half* __restrict__ out, int N,
                                               int aggBlocks,
                                               const float* __restrict__ W1,
                                               const float* __restrict__ W2,
                                               const float* __restrict__ W3,
                                               __half* __restrict__ t1,
                                               __half* __restrict__ t2,
                                               __half* __restrict__ t3,
                                               int K1, int N1, int K2, int N2,
                                               int K3, int N3) {
    if ((int)blockIdx.x >= aggBlocks) {
        // weight conversion partition
        int i = (blockIdx.x - aggBlocks) * blockDim.x + threadIdx.x;
        if (i < K1 * N1) {
            int k = i / N1, n = i % N1;
            t1[n * K1 + k] = __float2half_rn(W1[i]);
        }
        if (i < K2 * N2) {
            int k = i / N2, n = i % N2;
            t2[n * K2 + k] = __float2half_rn(W2[i]);
        }
        if (i < K3 * N3) {
            int k = i / N3, n = i % N3;
            t3[n * K3 + k] = __float2half_rn(W3[i]);
        }
        return;
    }
    // agg1 partition (R7 loop, unchanged)
    int node = (blockIdx.x * blockDim.x + threadIdx.x) >> 5;
    int lane = threadIdx.x & 31;
    if (node >= N) return;
    float w0 = dinv[node]; w0 *= w0;
    float4 a = ((const float4*)(X + (size_t)node * 128))[lane];
    float4 acc = make_float4(a.x * w0, a.y * w0, a.z * w0, a.w * w0);
    int j = rowptr[node], end = rowptr[node + 1];
    int2 e = (j < end) ? adj[j] : make_int2(0, 0);
    for (; j < end; j++) {
        int2 cur = e;
        if (j + 1 < end) e = adj[j + 1];
        float w = __int_as_float(cur.y);
        float4 s = ((const float4*)(X + (size_t)cur.x * 128))[lane];
        acc.x += w * s.x; acc.y += w * s.y;
        acc.z += w * s.z; acc.w += w * s.w;
    }
    ((uint2*)(out + (size_t)node * 128))[lane] =
        make_uint2(pack_h2(acc.x, acc.y), pack_h2(acc.z, acc.w));
}

// --- agg layer 2: fp16 h1 in (BN+ReLU fused via precomputed ss), fp16 out ---------
__global__ __launch_bounds__(256) void k_agg2(const int2* __restrict__ adj,
                                              const int* __restrict__ rowptr,
                                              const float* __restrict__ dinv,
                                              const __half* __restrict__ X,
                                              __half* __restrict__ out, int N,
                                              const float2* __restrict__ ss) {
    int node = (blockIdx.x * blockDim.x + threadIdx.x) >> 5;
    int lane = threadIdx.x & 31;
    if (node >= N) return;
    float2 sr[8];
#pragma unroll
    for (int j = 0; j < 8; j++) sr[j] = ss[lane * 8 + j];

    float acc[8];
    float w0 = dinv[node]; w0 *= w0;
    {
        uint4 u = ((const uint4*)(X + (size_t)node * 256))[lane];
        float2 f0 = unpack_h2(u.x), f1 = unpack_h2(u.y);
        float2 f2 = unpack_h2(u.z), f3 = unpack_h2(u.w);
        float f[8] = {f0.x, f0.y, f1.x, f1.y, f2.x, f2.y, f3.x, f3.y};
#pragma unroll
        for (int j = 0; j < 8; j++)
            acc[j] = w0 * fmaxf(fmaf(f[j], sr[j].x, sr[j].y), 0.f);
    }
    int j = rowptr[node], end = rowptr[node + 1];
    int2 e = (j < end) ? adj[j] : make_int2(0, 0);
    for (; j < end; j++) {
        int2 cur = e;
        if (j + 1 < end) e = adj[j + 1];
        float w = __int_as_float(cur.y);
        uint4 u = ((const uint4*)(X + (size_t)cur.x * 256))[lane];
        float2 f0 = unpack_h2(u.x), f1 = unpack_h2(u.y);
        float2 f2 = unpack_h2(u.z), f3 = unpack_h2(u.w);
        float f[8] = {f0.x, f0.y, f1.x, f1.y, f2.x, f2.y, f3.x, f3.y};
#pragma unroll
        for (int jj = 0; jj < 8; jj++)
            acc[jj] += w * fmaxf(fmaf(f[jj], sr[jj].x, sr[jj].y), 0.f);
    }
    uint4 o;
    o.x = pack_h2(acc[0], acc[1]);
    o.y = pack_h2(acc[2], acc[3]);
    o.z = pack_h2(acc[4], acc[5]);
    o.w = pack_h2(acc[6], acc[7]);
    ((uint4*)(out + (size_t)node * 256))[lane] = o;
}

// ---------------------------------------------------------------------------
// fp16 mma.sync pipelined GEMM: 128x128 tile, 8 warps (32x64), BK=32,
// cp.async 2-stage. Fused bias + fp32 BN stats, fp16 C.
// Last CTA (threadfence-reduction) computes ss from completed stats.
// ---------------------------------------------------------------------------
#define GBM 128
#define GBN 128
#define HASTR 40
#define HTSZ (128 * HASTR)
#define SMEM_H ((4 * HTSZ) * 2)
#define SMEM_FINH (SMEM_H + 512 * 8)

__global__ __launch_bounds__(256) void k_gemm_h(const __half* __restrict__ A,
                                                const __half* __restrict__ Bt,
                                                const float* __restrict__ bias,
                                                __half* __restrict__ C,
                                                float2* __restrict__ stats,
                                                int M, int N, int K,
                                                const float* __restrict__ gamma,
                                                const float* __restrict__ beta,
                                                float2* __restrict__ ss,
                                                float invM,
                                                int* __restrict__ done,
                                                int totalCTAs) {
    extern __shared__ __half smh[];
    __half* As = smh;
    __half* Bs = smh + 2 * HTSZ;

    const int tid  = threadIdx.x;
    const int lane = tid & 31;
    const int warpId = tid >> 5;
    const int warpM = warpId & 3;
    const int warpN = warpId >> 2;
    const int g = lane >> 2;
    const int t = lane & 3;
    const int bm = blockIdx.y * GBM;
    const int bn = blockIdx.x * GBN;

    const int l_row = tid >> 2;
    const int l_chk = (tid & 3) * 8;

    float4 acc[2][8];
#pragma unroll
    for (int i = 0; i < 2; i++)
#pragma unroll
        for (int j = 0; j < 8; j++)
            acc[i][j] = make_float4(0.f, 0.f, 0.f, 0.f);

    auto load_stage = [&](int stg, int k0) {
        __half* pa = As + stg * HTSZ;
        __half* pb = Bs + stg * HTSZ;
#pragma unroll
        for (int i = 0; i < 2; i++) {
            int row = i * 64 + l_row;
            int gm = bm + row;
            int ok = (gm < M) ? 16 : 0;
            int gmc = min(gm, M - 1);
            cp_async16(pa + row * HASTR + l_chk, A + (size_t)gmc * K + k0 + l_chk, ok);
        }
#pragma unroll
        for (int i = 0; i < 2; i++) {
            int row = i * 64 + l_row;
            cp_async16(pb + row * HASTR + l_chk, Bt + (size_t)(bn + row) * K + k0 + l_chk, 16);
        }
    };

    const int nk = K / 32;
    load_stage(0, 0);
    asm volatile("cp.async.commit_group;");

    for (int tk = 0; tk < nk; tk++) {
        if (tk + 1 < nk) {
            load_stage((tk + 1) & 1, (tk + 1) * 32);
            asm volatile("cp.async.commit_group;");
            asm volatile("cp.async.wait_group 1;");
        } else {
            asm volatile("cp.async.wait_group 0;");
        }
        __syncthreads();

        const __half* pa = As + (tk & 1) * HTSZ;
        const __half* pb = Bs + (tk & 1) * HTSZ;
#pragma unroll
        for (int kk = 0; kk < 32; kk += 16) {
            uint32_t afrag[2][4];
            uint32_t bfrag[8][2];
#pragma unroll
            for (int im = 0; im < 2; im++) {
                const __half* base = pa + (warpM * 32 + im * 16 + g) * HASTR + kk + 2 * t;
                afrag[im][0] = *(const uint32_t*)(base);
                afrag[im][1] = *(const uint32_t*)(base + 8 * HASTR);
                afrag[im][2] = *(const uint32_t*)(base + 8);
                afrag[im][3] = *(const uint32_t*)(base + 8 * HASTR + 8);
            }
#pragma unroll
            for (int jn = 0; jn < 8; jn++) {
                const __half* base = pb + (warpN * 64 + jn * 8 + g) * HASTR + kk + 2 * t;
                bfrag[jn][0] = *(const uint32_t*)(base);
                bfrag[jn][1] = *(const uint32_t*)(base + 8);
            }
#pragma unroll
            for (int im = 0; im < 2; im++)
#pragma unroll
                for (int jn = 0; jn < 8; jn++) {
                    float4& c = acc[im][jn];
                    asm volatile(
                        "mma.sync.aligned.m16n8k16.row.col.f32.f16.f16.f32 "
                        "{%0,%1,%2,%3}, {%4,%5,%6,%7}, {%8,%9}, {%0,%1,%2,%3};"
                        : "+f"(c.x), "+f"(c.y), "+f"(c.z), "+f"(c.w)
                        : "r"(afrag[im][0]), "r"(afrag[im][1]),
                          "r"(afrag[im][2]), "r"(afrag[im][3]),
                          "r"(bfrag[jn][0]), "r"(bfrag[jn][1]));
                }
        }
        __syncthreads();
    }

#pragma unroll
    for (int jn = 0; jn < 8; jn++) {
        int col = bn + warpN * 64 + jn * 8 + 2 * t;
        float bx = bias[col], by = bias[col + 1];
        float s0 = 0.f, q0 = 0.f, s1 = 0.f, q1 = 0.f;
#pragma unroll
        for (int im = 0; im < 2; im++) {
            int row0 = bm + warpM * 32 + im * 16 + g;
            float4 c = acc[im][jn];
            if (row0 < M) {
                float ox = c.x + bx, oy = c.y + by;
                *(uint32_t*)(C + (size_t)row0 * N + col) = pack_h2(ox, oy);
                s0 += ox; q0 += ox * ox; s1 += oy; q1 += oy * oy;
            }
            if (row0 + 8 < M) {
                float oz = c.z + bx, ow = c.w + by;
                *(uint32_t*)(C + (size_t)(row0 + 8) * N + col) = pack_h2(oz, ow);
                s0 += oz; q0 += oz * oz; s1 += ow; q1 += ow * ow;
            }
        }
#pragma unroll
        for (int m = 4; m < 32; m <<= 1) {
            s0 += __shfl_xor_sync(0xffffffffu, s0, m);
            q0 += __shfl_xor_sync(0xffffffffu, q0, m);
            s1 += __shfl_xor_sync(0xffffffffu, s1, m);
            q1 += __shfl_xor_sync(0xffffffffu, q1, m);
        }
        if (g == 0) {
            red_add_v2(&stats[col], s0, q0);
            red_add_v2(&stats[col + 1], s1, q1);
        }
    }

    // --- last-CTA bnprep: stats -> ss (threadfence reduction pattern) ---
    __shared__ int s_last;
    __syncthreads();                       // all stats reds issued block-wide
    if (tid == 0) {
        __threadfence();                   // order this CTA's writes (sync'd in)
        int prev = atomicAdd(done, 1);
        s_last = (prev == totalCTAs - 1);
    }
    __syncthreads();
    if (s_last) {
        __threadfence();                   // acquire: see all CTAs' stats
        for (int c = tid; c < N; c += 256)
            ss[c] = bn_ss(stats[c], gamma[c], beta[c], invM);
        if (tid == 0) *done = 0;           // reset for next use / graph replay
    }
}

// ---------------------------------------------------------------------------
// Final fp16 GEMM: A = raw fp16 h2, BN2+ReLU applied at frag build from
// precomputed ss (staged to smem), B = fp16 Wl^T. fp32 out.
// ---------------------------------------------------------------------------
__global__ __launch_bounds__(256) void k_gemm_finh(const __half* __restrict__ A,
                                                   const __half* __restrict__ Bt,
                                                   const float* __restrict__ bias,
                                                   float* __restrict__ C,
                                                   const float2* __restrict__ ssA,
                                                   int M, int N, int K) {
    extern __shared__ __half smh[];
    __half* As = smh;
    __half* Bs = smh + 2 * HTSZ;
    float2* ssm = (float2*)(smh + 4 * HTSZ);

    const int tid  = threadIdx.x;
    const int lane = tid & 31;
    const int warpId = tid >> 5;
    const int warpM = warpId & 3;
    const int warpN = warpId >> 2;
    const int g = lane >> 2;
    const int t = lane & 3;
    const int bm = blockIdx.y * GBM;
    const int bn = blockIdx.x * GBN;

    for (int c = tid; c < K; c += 256) ssm[c] = ssA[c];

    const int l_row = tid >> 2;
    const int l_chk = (tid & 3) * 8;

    float4 acc[2][8];
#pragma unroll
    for (int i = 0; i < 2; i++)
#pragma unroll
        for (int j = 0; j < 8; j++)
            acc[i][j] = make_float4(0.f, 0.f, 0.f, 0.f);

    auto load_stage = [&](int stg, int k0) {
        __half* pa = As + stg * HTSZ;
        __half* pb = Bs + stg * HTSZ;
#pragma unroll
        for (int i = 0; i < 2; i++) {
            int row = i * 64 + l_row;
            int gm = bm + row;
            int ok = (gm < M) ? 16 : 0;
            int gmc = min(gm, M - 1);
            cp_async16(pa + row * HASTR + l_chk, A + (size_t)gmc * K + k0 + l_chk, ok);
        }
#pragma unroll
        for (int i = 0; i < 2; i++) {
            int row = i * 64 + l_row;
            cp_async16(pb + row * HASTR + l_chk, Bt + (size_t)(bn + row) * K + k0 + l_chk, 16);
        }
    };

    const int nk = K / 32;
    load_stage(0, 0);
    asm volatile("cp.async.commit_group;");

    for (int tk = 0; tk < nk; tk++) {
        if (tk + 1 < nk) {
            load_stage((tk + 1) & 1, (tk + 1) * 32);
            asm volatile("cp.async.commit_group;");
            asm volatile("cp.async.wait_group 1;");
        } else {
            asm volatile("cp.async.wait_group 0;");
        }
        __syncthreads();

        const __half* pa = As + (tk & 1) * HTSZ;
        const __half* pb = Bs + (tk & 1) * HTSZ;
        const int kbase = tk * 32;
#pragma unroll
        for (int kk = 0; kk < 32; kk += 16) {
            int kc = kbase + kk + 2 * t;
            float2 s0 = ssm[kc],     s1 = ssm[kc + 1];
            float2 s2 = ssm[kc + 8], s3 = ssm[kc + 9];
            uint32_t afrag[2][4];
            uint32_t bfrag[8][2];
#pragma unroll
            for (int im = 0; im < 2; im++) {
                const __half* base = pa + (warpM * 32 + im * 16 + g) * HASTR + kk + 2 * t;
                float2 f0 = unpack_h2(*(const uint32_t*)(base));
                float2 f1 = unpack_h2(*(const uint32_t*)(base + 8 * HASTR));
                float2 f2 = unpack_h2(*(const uint32_t*)(base + 8));
                float2 f3 = unpack_h2(*(const uint32_t*)(base + 8 * HASTR + 8));
                afrag[im][0] = pack_h2(fmaxf(fmaf(f0.x, s0.x, s0.y), 0.f),
                                       fmaxf(fmaf(f0.y, s1.x, s1.y), 0.f));
                afrag[im][1] = pack_h2(fmaxf(fmaf(f1.x, s0.x, s0.y), 0.f),
                                       fmaxf(fmaf(f1.y, s1.x, s1.y), 0.f));
                afrag[im][2] = pack_h2(fmaxf(fmaf(f2.x, s2.x, s2.y), 0.f),
                                       fmaxf(fmaf(f2.y, s3.x, s3.y), 0.f));
                afrag[im][3] = pack_h2(fmaxf(fmaf(f3.x, s2.x, s2.y), 0.f),
                                       fmaxf(fmaf(f3.y, s3.x, s3.y), 0.f));
            }
#pragma unroll
            for (int jn = 0; jn < 8; jn++) {
                const __half* base = pb + (warpN * 64 + jn * 8 + g) * HASTR + kk + 2 * t;
                bfrag[jn][0] = *(const uint32_t*)(base);
                bfrag[jn][1] = *(const uint32_t*)(base + 8);
            }
#pragma unroll
            for (int im = 0; im < 2; im++)
#pragma unroll
                for (int jn = 0; jn < 8; jn++) {
                    float4& c = acc[im][jn];
                    asm volatile(
                        "mma.sync.aligned.m16n8k16.row.col.f32.f16.f16.f32 "
                        "{%0,%1,%2,%3}, {%4,%5,%6,%7}, {%8,%9}, {%0,%1,%2,%3};"
                        : "+f"(c.x), "+f"(c.y), "+f"(c.z), "+f"(c.w)
                        : "r"(afrag[im][0]), "r"(afrag[im][1]),
                          "r"(afrag[im][2]), "r"(afrag[im][3]),
                          "r"(bfrag[jn][0]), "r"(bfrag[jn][1]));
                }
        }
        __syncthreads();
    }

#pragma unroll
    for (int jn = 0; jn < 8; jn++) {
        int col = bn + warpN * 64 + jn * 8 + 2 * t;
        float bx = bias[col], by = bias[col + 1];
#pragma unroll
        for (int im = 0; im < 2; im++) {
            int row0 = bm + warpM * 32 + im * 16 + g;
            float4 c = acc[im][jn];
            if (row0 < M)
                *(float2*)(C + (size_t)row0 * N + col) = make_float2(c.x + bx, c.y + by);
            if (row0 + 8 < M)
                *(float2*)(C + (size_t)(row0 + 8) * N + col) = make_float2(c.z + bx, c.w + by);
        }
    }
}

// ---------------------------------------------------------------------------

extern "C" void kernel_launch(void* const* d_in, const int* in_sizes, int n_in,
                              void* d_out, int out_size) {
    const float* x      = (const float*)d_in[0];
    const void*  ei     = d_in[1];
    const float* W1     = (const float*)d_in[2];
    const float* b1     = (const float*)d_in[3];
    const float* gamma1 = (const float*)d_in[4];
    const float* beta1  = (const float*)d_in[5];
    const float* W2     = (const float*)d_in[6];
    const float* b2     = (const float*)d_in[7];
    const float* gamma2 = (const float*)d_in[8];
    const float* beta2  = (const float*)d_in[9];
    const float* Wl     = (const float*)d_in[10];
    const float* bl     = (const float*)d_in[11];

    const int H1   = in_sizes[3];
    const int H2   = in_sizes[7];
    const int DOUT = in_sizes[11];
    const int DIN  = in_sizes[2] / H1;
    const int N    = in_sizes[0] / DIN;
    const long long E = in_sizes[1] / 2;
    const float invM = 1.0f / (float)N;

    float *dinv;
    __half *agg1h, *agg2h, *h1, *h2, *w1t, *w2t, *wlt;
    float2 *stats1, *stats2, *ss1, *ss2;
    int *cnt, *rowptr, *cursor, *flag, *bsum, *done;
    int2* adj;
    cudaGetSymbolAddress((void**)&dinv,   g_dinv);
    cudaGetSymbolAddress((void**)&cnt,    g_cnt);
    cudaGetSymbolAddress((void**)&rowptr, g_rowptr);
    cudaGetSymbolAddress((void**)&cursor, g_cursor);
    cudaGetSymbolAddress((void**)&bsum,   g_bsum);
    cudaGetSymbolAddress((void**)&adj,    g_adj);
    cudaGetSymbolAddress((void**)&agg1h,  g_agg1h);
    cudaGetSymbolAddress((void**)&agg2h,  g_agg2h);
    cudaGetSymbolAddress((void**)&h1,     g_h1);
    cudaGetSymbolAddress((void**)&h2,     g_h2);
    cudaGetSymbolAddress((void**)&w1t,    g_w1t);
    cudaGetSymbolAddress((void**)&w2t,    g_w2t);
    cudaGetSymbolAddress((void**)&wlt,    g_wlt);
    cudaGetSymbolAddress((void**)&stats1, g_stats1);
    cudaGetSymbolAddress((void**)&stats2, g_stats2);
    cudaGetSymbolAddress((void**)&ss1,    g_ss1);
    cudaGetSymbolAddress((void**)&ss2,    g_ss2);
    cudaGetSymbolAddress((void**)&flag,   g_flag32);
    cudaGetSymbolAddress((void**)&done,   g_done);

    float* out = (float*)d_out;

    cudaFuncSetAttribute(k_gemm_h,    cudaFuncAttributeMaxDynamicSharedMemorySize, SMEM_H);
    cudaFuncSetAttribute(k_gemm_finh, cudaFuncAttributeMaxDynamicSharedMemorySize, SMEM_FINH);

    const int scanBlocks = (N + SCAN_BLK - 1) / SCAN_BLK;
    const int aggBlocks = (int)(((long long)N * 32 + 255) / 256);
    const int cvtBlocks = (H1 * H2 + 255) / 256;
    const int mBlocks = (N + GBM - 1) / GBM;

    // prep (5 launches)
    k_prep0<<<(N + 255) / 256, 256>>>((const int*)ei, E, cnt, N, stats1, stats2, H1, H2, flag);
    k_count<<<1024, 256>>>(ei, E, flag, cnt);
    k_scan_red<<<scanBlocks, SCAN_BLK>>>(cnt, bsum, N);
    k_scan_apply<<<scanBlocks, SCAN_BLK>>>(cnt, bsum, scanBlocks, rowptr, cursor, dinv, N);
    k_fill<<<1024, 256>>>(ei, E, flag, dinv, cursor, adj);

    // agg1 + weight cvt fused (1 launch)
    k_agg1w<<<aggBlocks + cvtBlocks, 256>>>(adj, rowptr, dinv, x, agg1h, N, aggBlocks,
                                            W1, W2, Wl, w1t, w2t, wlt,
                                            DIN, H1, H1, H2, H2, DOUT);

    // layer-1 GEMM with last-CTA bnprep (1 launch)
    {
        dim3 grid(H1 / GBN, mBlocks);
        k_gemm_h<<<grid, 256, SMEM_H>>>(agg1h, w1t, b1, h1, stats1, N, H1, DIN,
                                        gamma1, beta1, ss1, invM,
                                        done, (H1 / GBN) * mBlocks);
    }

    // layer 2 (2 launches)
    k_agg2<<<aggBlocks, 256>>>(adj, rowptr, dinv, h1, agg2h, N, ss1);
    {
        dim3 grid(H2 / GBN, mBlocks);
        k_gemm_h<<<grid, 256, SMEM_H>>>(agg2h, w2t, b2, h2, stats2, N, H2, H1,
                                        gamma2, beta2, ss2, invM,
                                        done, (H2 / GBN) * mBlocks);
    }

    // final projection (1 launch)
    {
        dim3 grid(DOUT / GBN, mBlocks);
        k_gemm_finh<<<grid, 256, SMEM_FINH>>>(h2, wlt, bl, out, ss2, N, DOUT, H2);
    }
}